// round 6
// baseline (speedup 1.0000x reference)
#include <cuda_runtime.h>
#include <cstdint>

// ---------------------------------------------------------------------------
// Problem constants
// ---------------------------------------------------------------------------
#define BATCH 8192
#define INF   4096
#define OUTF  4096
#define EPS   1e-4f
#define KW    (INF / 32)          // 128 words per row

// ---------------------------------------------------------------------------
// Scratch (device globals — no allocation allowed)
// ---------------------------------------------------------------------------
__device__ uint32_t g_xb[(size_t)BATCH * KW];   // 4 MB packed sign bits
__device__ uint32_t g_wb[(size_t)OUTF * KW];    // 2 MB
__device__ float g_wscale[OUTF];
__device__ float g_thr[INF];
__device__ uint32_t g_flip[INF];
__device__ float g_psum[32 * INF];
__device__ float g_psq[32 * INF];

// ---------------------------------------------------------------------------
// helpers
// ---------------------------------------------------------------------------
__device__ __forceinline__ uint32_t smem_u32(const void* p) {
    uint32_t a;
    asm("{ .reg .u64 t; cvta.to.shared.u64 t, %1; cvt.u32.u64 %0, t; }"
        : "=r"(a) : "l"(p));
    return a;
}
__device__ __forceinline__ void cp_async16(uint32_t dst, const void* src) {
    asm volatile("cp.async.cg.shared.global [%0], [%1], 16;"
                 :: "r"(dst), "l"(src) : "memory");
}
__device__ __forceinline__ void cp_commit() {
    asm volatile("cp.async.commit_group;" ::: "memory");
}
template <int N>
__device__ __forceinline__ void cp_wait() {
    asm volatile("cp.async.wait_group %0;" :: "n"(N) : "memory");
}
__device__ __forceinline__ uint4 lds128(uint32_t addr) {
    uint4 v;
    asm volatile("ld.shared.v4.b32 {%0, %1, %2, %3}, [%4];"
                 : "=r"(v.x), "=r"(v.y), "=r"(v.z), "=r"(v.w) : "r"(addr));
    return v;
}
// acc += p * one  (one == 1 at runtime, opaque to ptxas -> IMAD on fma pipe)
__device__ __forceinline__ void mad_acc(int& acc, int p, int one) {
    asm("mad.lo.s32 %0, %1, %2, %0;" : "+r"(acc) : "r"(p), "r"(one));
}
__device__ __forceinline__ void stg_cs(float* p, float v) {
    asm volatile("st.global.cs.f32 [%0], %1;" :: "l"(p), "f"(v) : "memory");
}

// ---------------------------------------------------------------------------
// Kernel 0: dummy (shifts the GEMM into ncu's capture slot)
// ---------------------------------------------------------------------------
__global__ void dummy_kernel() {}

// ---------------------------------------------------------------------------
// Kernel 1a: column partial sums (deterministic two-pass stats)
// ---------------------------------------------------------------------------
__global__ __launch_bounds__(256) void stats_partial_kernel(const float* __restrict__ x) {
    int c = blockIdx.x * 256 + threadIdx.x;
    int rc = blockIdx.y;
    float s = 0.f, q = 0.f;
    int r0 = rc * (BATCH / 32);
#pragma unroll 4
    for (int r = r0; r < r0 + (BATCH / 32); ++r) {
        float v = x[(size_t)r * INF + c];
        s += v;
        q += v * v;
    }
    g_psum[rc * INF + c] = s;
    g_psq[rc * INF + c] = q;
}

// Kernel 1b: finalize -> per-column threshold + flip
__global__ __launch_bounds__(256) void stats_finalize_kernel(const float* __restrict__ gamma,
                                                             const float* __restrict__ beta) {
    int c = blockIdx.x * 256 + threadIdx.x;
    float s = 0.f, q = 0.f;
    for (int rc = 0; rc < 32; ++rc) {
        s += g_psum[rc * INF + c];
        q += g_psq[rc * INF + c];
    }
    float mu = s * (1.0f / BATCH);
    float var = q * (1.0f / BATCH) - mu * mu;
    float rstd = rsqrtf(var + EPS);
    float sc = gamma[c] * rstd;
    float t;
    uint32_t fl;
    if (sc > 0.f) { t = mu - beta[c] / sc; fl = 0u; }
    else if (sc < 0.f) { t = mu - beta[c] / sc; fl = 1u; }
    else {
        t = (beta[c] > 0.f) ? __int_as_float(0xff800000)   // -inf -> always 1
                            : __int_as_float(0x7f800000);  // +inf -> always 0
        fl = 0u;
    }
    g_thr[c] = t;
    g_flip[c] = fl;
}

// ---------------------------------------------------------------------------
// Kernel 2: pack activation sign bits via ballot.
// ---------------------------------------------------------------------------
__global__ __launch_bounds__(256) void binx_pack(const float* __restrict__ x) {
    int row = blockIdx.x;
    int warp = threadIdx.x >> 5;
    int lane = threadIdx.x & 31;
    int c0 = (blockIdx.y * 8 + warp) * 128;
    const float* xr = x + (size_t)row * INF + c0 + lane;
    uint32_t* ow = g_xb + (size_t)row * KW + (blockIdx.y * 8 + warp) * 4;
#pragma unroll
    for (int j = 0; j < 4; ++j) {
        int c = c0 + lane + 32 * j;
        float v = xr[32 * j];
        uint32_t bit = ((v > g_thr[c]) ? 1u : 0u) ^ g_flip[c];
        uint32_t word = __ballot_sync(0xffffffffu, bit);
        if (lane == 0) ow[j] = word;
    }
}

// ---------------------------------------------------------------------------
// Kernel 3: pack weight sign bits (row-centered) + per-row L1 scale.
// ---------------------------------------------------------------------------
__global__ __launch_bounds__(256) void binw_pack(const float* __restrict__ w) {
    __shared__ float red[256];
    int row = blockIdx.x;
    int tid = threadIdx.x;
    int warp = tid >> 5;
    int lane = tid & 31;
    const float* wr = w + (size_t)row * INF;

    float vals[16];
    float s = 0.f;
#pragma unroll
    for (int j = 0; j < 16; ++j) {
        vals[j] = wr[warp * 512 + lane + 32 * j];
        s += vals[j];
    }
    red[tid] = s;
    __syncthreads();
    for (int o = 128; o > 0; o >>= 1) {
        if (tid < o) red[tid] += red[tid + o];
        __syncthreads();
    }
    float mean = red[0] * (1.0f / INF);
    __syncthreads();

    float a = 0.f;
#pragma unroll
    for (int j = 0; j < 16; ++j) {
        float d = vals[j] - mean;
        a += fabsf(fminf(fmaxf(d, -1.f), 1.f));
        uint32_t word = __ballot_sync(0xffffffffu, d > 0.f);
        if (lane == 0) g_wb[(size_t)row * KW + warp * 16 + j] = word;
    }
    red[tid] = a;
    __syncthreads();
    for (int o = 128; o > 0; o >>= 1) {
        if (tid < o) red[tid] += red[tid + o];
        __syncthreads();
    }
    if (tid == 0) g_wscale[row] = red[0] * (1.0f / INF);
}

// ---------------------------------------------------------------------------
// Kernel 4: XNOR-popcount GEMM, 512 threads.
//   CTA tile 128(M) x 256(N), 16 warps (warp 32Mx64N), thread 8x8.
//   K chunks of 32 words, 3-stage cp.async ring, pitch 144B.
//   alu pipe: XOR+POPC only; IMAD accumulate on fma pipe; B-frag prefetch.
// ---------------------------------------------------------------------------
#define KC 32
#define PITCH 144
#define TROWS (128 + 256)                  // A rows + B rows per stage
#define STG_BYTES (TROWS * PITCH)          // 55296
#define NST 3
#define NCHUNK (KW / KC)                   // 4
#define GEMM_SMEM (NST * STG_BYTES)        // 165888

__global__ __launch_bounds__(512, 1) void gemm_kernel(const float* __restrict__ bias,
                                                      float* __restrict__ out) {
    extern __shared__ char smem_raw[];
    const uint32_t sbase = smem_u32(smem_raw);

    const int tid = threadIdx.x;
    const int wid = tid >> 5;
    const int lane = tid & 31;
    const int wm = wid >> 2;        // 0..3  (M warp)
    const int wn = wid & 3;         // 0..3  (N warp)
    const int tm = lane >> 3;       // 0..3
    const int tn = lane & 7;        // 0..7
    const int tile_n = blockIdx.x;  // 0..15
    const int tile_m = blockIdx.y;  // 0..63
    const int one = (int)(blockDim.x >> 9);   // == 1, opaque to ptxas

    // ---- producer mapping: 6 x 16B chunks per thread per stage ----------
    const int r0 = tid >> 3;        // 0..63
    const int col16 = tid & 7;
    const uint32_t* gA = g_xb + ((size_t)tile_m * 128 + r0) * KW + col16 * 4;
    const uint32_t* gB = g_wb + ((size_t)tile_n * 256 + r0) * KW + col16 * 4;
    const uint32_t sA = (uint32_t)r0 * PITCH + (uint32_t)col16 * 16;
    const uint32_t sB = (uint32_t)(128 + r0) * PITCH + (uint32_t)col16 * 16;

#define FILL_STAGE(stg_off, kc_words)                                        \
    do {                                                                     \
        uint32_t _b = sbase + (stg_off);                                     \
        const uint32_t* _ga = gA + (kc_words);                               \
        const uint32_t* _gb = gB + (kc_words);                               \
        cp_async16(_b + sA, _ga);                                            \
        cp_async16(_b + sA + 64u * PITCH, _ga + (size_t)64 * KW);            \
        cp_async16(_b + sB, _gb);                                            \
        cp_async16(_b + sB + 64u * PITCH, _gb + (size_t)64 * KW);            \
        cp_async16(_b + sB + 128u * PITCH, _gb + (size_t)128 * KW);          \
        cp_async16(_b + sB + 192u * PITCH, _gb + (size_t)192 * KW);          \
    } while (0)

    // prologue: fill stages 0, 1
#pragma unroll
    for (int s = 0; s < NST - 1; ++s) {
        FILL_STAGE(s * STG_BYTES, s * KC);
        cp_commit();
    }

    int acc[8][8];
#pragma unroll
    for (int i = 0; i < 8; ++i)
#pragma unroll
        for (int j = 0; j < 8; ++j) acc[i][j] = 0;

    const uint32_t aoff = (uint32_t)(wm * 32 + tm) * PITCH;
    const uint32_t boff = (uint32_t)(128 + wn * 64 + tn) * PITCH;

    for (int kc = 0; kc < NCHUNK; ++kc) {
        cp_wait<NST - 2>();
        __syncthreads();

        int ps = kc + NST - 1;
        if (ps < NCHUNK) FILL_STAGE((ps % NST) * STG_BYTES, ps * KC);
        cp_commit();

        const uint32_t stg = sbase + (kc % NST) * STG_BYTES;
#pragma unroll 1
        for (int k4 = 0; k4 < KC / 4; ++k4) {
            const uint32_t kb = (uint32_t)k4 * 16;
            uint4 a[8];
#pragma unroll
            for (int i = 0; i < 8; ++i)
                a[i] = lds128(stg + aoff + (uint32_t)(i * 4) * PITCH + kb);

            uint4 b = lds128(stg + boff + kb);   // prefetch j=0
#pragma unroll
            for (int j = 0; j < 8; ++j) {
                uint4 bc = b;
                if (j < 7)
                    b = lds128(stg + boff + (uint32_t)((j + 1) * 8) * PITCH + kb);
#pragma unroll
                for (int i = 0; i < 8; ++i) {
                    mad_acc(acc[i][j], __popc(a[i].x ^ bc.x), one);
                    mad_acc(acc[i][j], __popc(a[i].y ^ bc.y), one);
                    mad_acc(acc[i][j], __popc(a[i].z ^ bc.z), one);
                    mad_acc(acc[i][j], __popc(a[i].w ^ bc.w), one);
                }
            }
        }
    }

    // ---- epilogue (streaming stores) -----------------------------------
    const int mb = tile_m * 128 + wm * 32 + tm;
    const int nb = tile_n * 256 + wn * 64 + tn;
#pragma unroll
    for (int j = 0; j < 8; ++j) {
        int n = nb + 8 * j;
        float bv = __ldg(bias + n);
        float sv = g_wscale[n];
#pragma unroll
        for (int i = 0; i < 8; ++i) {
            int m = mb + 4 * i;
            float v = (float)(INF - 2 * acc[i][j]);
            stg_cs(out + (size_t)m * OUTF + n, fmaxf((v + bv) * sv, 0.f));
        }
    }
}

// ---------------------------------------------------------------------------
// Launcher
// ---------------------------------------------------------------------------
extern "C" void kernel_launch(void* const* d_in, const int* in_sizes, int n_in,
                              void* d_out, int out_size) {
    (void)in_sizes; (void)n_in; (void)out_size;
    const float* x     = (const float*)d_in[0];
    const float* gamma = (const float*)d_in[1];
    const float* beta  = (const float*)d_in[2];
    const float* w     = (const float*)d_in[3];
    const float* bias  = (const float*)d_in[4];
    float* out = (float*)d_out;

    dummy_kernel<<<1, 32>>>();          // launch 0: shifts GEMM into ncu slot 5
    stats_partial_kernel<<<dim3(16, 32), 256>>>(x);
    stats_finalize_kernel<<<16, 256>>>(gamma, beta);
    binx_pack<<<dim3(BATCH, 4), 256>>>(x);
    binw_pack<<<OUTF, 256>>>(w);

    cudaFuncSetAttribute(gemm_kernel, cudaFuncAttributeMaxDynamicSharedMemorySize, GEMM_SMEM);
    gemm_kernel<<<dim3(OUTF / 256, BATCH / 128), 512, GEMM_SMEM>>>(bias, out);
}

// round 7
// speedup vs baseline: 1.0147x; 1.0147x over previous
#include <cuda_runtime.h>
#include <cstdint>

// ---------------------------------------------------------------------------
// Problem constants
// ---------------------------------------------------------------------------
#define BATCH 8192
#define INF   4096
#define OUTF  4096
#define EPS   1e-4f
#define KW    (INF / 32)          // 128 words per row

// ---------------------------------------------------------------------------
// Scratch (device globals — no allocation allowed)
// ---------------------------------------------------------------------------
__device__ uint32_t g_xb[(size_t)BATCH * KW];   // 4 MB packed sign bits
__device__ uint32_t g_wb[(size_t)OUTF * KW];    // 2 MB
__device__ float g_wscale[OUTF];
__device__ float g_thr[INF];
__device__ uint32_t g_flip[INF];
__device__ float g_psum[32 * INF];
__device__ float g_psq[32 * INF];

// ---------------------------------------------------------------------------
// helpers
// ---------------------------------------------------------------------------
__device__ __forceinline__ uint32_t smem_u32(const void* p) {
    uint32_t a;
    asm("{ .reg .u64 t; cvta.to.shared.u64 t, %1; cvt.u32.u64 %0, t; }"
        : "=r"(a) : "l"(p));
    return a;
}
__device__ __forceinline__ void cp_async16(uint32_t dst, const void* src) {
    asm volatile("cp.async.cg.shared.global [%0], [%1], 16;"
                 :: "r"(dst), "l"(src) : "memory");
}
__device__ __forceinline__ void cp_commit() {
    asm volatile("cp.async.commit_group;" ::: "memory");
}
template <int N>
__device__ __forceinline__ void cp_wait() {
    asm volatile("cp.async.wait_group %0;" :: "n"(N) : "memory");
}
__device__ __forceinline__ uint4 lds128(uint32_t addr) {
    uint4 v;
    asm volatile("ld.shared.v4.b32 {%0, %1, %2, %3}, [%4];"
                 : "=r"(v.x), "=r"(v.y), "=r"(v.z), "=r"(v.w) : "r"(addr));
    return v;
}
// acc += p * one  (one == 1 at runtime, opaque to ptxas -> IMAD on fma pipe)
__device__ __forceinline__ void mad_acc(int& acc, int p, int one) {
    asm("mad.lo.s32 %0, %1, %2, %0;" : "+r"(acc) : "r"(p), "r"(one));
}

// ---------------------------------------------------------------------------
// Kernel 1a: column partial sums (deterministic two-pass stats)
// ---------------------------------------------------------------------------
__global__ __launch_bounds__(256) void stats_partial_kernel(const float* __restrict__ x) {
    int c = blockIdx.x * 256 + threadIdx.x;
    int rc = blockIdx.y;
    float s = 0.f, q = 0.f;
    int r0 = rc * (BATCH / 32);
#pragma unroll 4
    for (int r = r0; r < r0 + (BATCH / 32); ++r) {
        float v = x[(size_t)r * INF + c];
        s += v;
        q += v * v;
    }
    g_psum[rc * INF + c] = s;
    g_psq[rc * INF + c] = q;
}

// Kernel 1b: finalize -> per-column threshold + flip
__global__ __launch_bounds__(256) void stats_finalize_kernel(const float* __restrict__ gamma,
                                                             const float* __restrict__ beta) {
    int c = blockIdx.x * 256 + threadIdx.x;
    float s = 0.f, q = 0.f;
    for (int rc = 0; rc < 32; ++rc) {
        s += g_psum[rc * INF + c];
        q += g_psq[rc * INF + c];
    }
    float mu = s * (1.0f / BATCH);
    float var = q * (1.0f / BATCH) - mu * mu;
    float rstd = rsqrtf(var + EPS);
    float sc = gamma[c] * rstd;
    float t;
    uint32_t fl;
    if (sc > 0.f) { t = mu - beta[c] / sc; fl = 0u; }
    else if (sc < 0.f) { t = mu - beta[c] / sc; fl = 1u; }
    else {
        t = (beta[c] > 0.f) ? __int_as_float(0xff800000)   // -inf -> always 1
                            : __int_as_float(0x7f800000);  // +inf -> always 0
        fl = 0u;
    }
    g_thr[c] = t;
    g_flip[c] = fl;
}

// ---------------------------------------------------------------------------
// Kernel 2 (merged): pack activation bits (blocks [0, 32768)) and
//                    weight bits + L1 scale (blocks [32768, 36864)).
// Merged so the GEMM is the 4th launch (ncu capture slot).
// ---------------------------------------------------------------------------
__global__ __launch_bounds__(256) void pack_kernel(const float* __restrict__ x,
                                                   const float* __restrict__ w) {
    int bid = blockIdx.x;
    if (bid < BATCH * 4) {
        // ---------------- binx part ----------------
        int row = bid >> 2;
        int yg = bid & 3;
        int warp = threadIdx.x >> 5;
        int lane = threadIdx.x & 31;
        int c0 = (yg * 8 + warp) * 128;
        const float* xr = x + (size_t)row * INF + c0 + lane;
        uint32_t* ow = g_xb + (size_t)row * KW + (yg * 8 + warp) * 4;
#pragma unroll
        for (int j = 0; j < 4; ++j) {
            int c = c0 + lane + 32 * j;
            float v = xr[32 * j];
            uint32_t bit = ((v > g_thr[c]) ? 1u : 0u) ^ g_flip[c];
            uint32_t word = __ballot_sync(0xffffffffu, bit);
            if (lane == 0) ow[j] = word;
        }
    } else {
        // ---------------- binw part ----------------
        __shared__ float red[256];
        int row = bid - BATCH * 4;
        int tid = threadIdx.x;
        int warp = tid >> 5;
        int lane = tid & 31;
        const float* wr = w + (size_t)row * INF;

        float vals[16];
        float s = 0.f;
#pragma unroll
        for (int j = 0; j < 16; ++j) {
            vals[j] = wr[warp * 512 + lane + 32 * j];
            s += vals[j];
        }
        red[tid] = s;
        __syncthreads();
        for (int o = 128; o > 0; o >>= 1) {
            if (tid < o) red[tid] += red[tid + o];
            __syncthreads();
        }
        float mean = red[0] * (1.0f / INF);
        __syncthreads();

        float a = 0.f;
#pragma unroll
        for (int j = 0; j < 16; ++j) {
            float d = vals[j] - mean;
            a += fabsf(fminf(fmaxf(d, -1.f), 1.f));
            uint32_t word = __ballot_sync(0xffffffffu, d > 0.f);
            if (lane == 0) g_wb[(size_t)row * KW + warp * 16 + j] = word;
        }
        red[tid] = a;
        __syncthreads();
        for (int o = 128; o > 0; o >>= 1) {
            if (tid < o) red[tid] += red[tid + o];
            __syncthreads();
        }
        if (tid == 0) g_wscale[row] = red[0] * (1.0f / INF);
    }
}

// ---------------------------------------------------------------------------
// Kernel 4: XNOR-popcount GEMM, 512 threads (R5-best inner loop).
//   CTA tile 128(M) x 256(N), 16 warps (warp 32Mx64N), thread 8x8.
//   K chunks of 32 words, 3-stage cp.async ring, pitch 144B.
//   alu pipe: XOR+POPC only; IMAD accumulate on fma pipe.
// ---------------------------------------------------------------------------
#define KC 32
#define PITCH 144
#define TROWS (128 + 256)                  // A rows + B rows per stage
#define STG_BYTES (TROWS * PITCH)          // 55296
#define NST 3
#define NCHUNK (KW / KC)                   // 4
#define GEMM_SMEM (NST * STG_BYTES)        // 165888

__global__ __launch_bounds__(512, 1) void gemm_kernel(const float* __restrict__ bias,
                                                      float* __restrict__ out) {
    extern __shared__ char smem_raw[];
    const uint32_t sbase = smem_u32(smem_raw);

    const int tid = threadIdx.x;
    const int wid = tid >> 5;
    const int lane = tid & 31;
    const int wm = wid >> 2;        // 0..3  (M warp)
    const int wn = wid & 3;         // 0..3  (N warp)
    const int tm = lane >> 3;       // 0..3
    const int tn = lane & 7;        // 0..7
    const int tile_n = blockIdx.x;  // 0..15
    const int tile_m = blockIdx.y;  // 0..63
    const int one = (int)(blockDim.x >> 9);   // == 1, opaque to ptxas

    // ---- producer mapping: 6 x 16B chunks per thread per stage ----------
    const int r0 = tid >> 3;        // 0..63
    const int col16 = tid & 7;
    const uint32_t* gA = g_xb + ((size_t)tile_m * 128 + r0) * KW + col16 * 4;
    const uint32_t* gB = g_wb + ((size_t)tile_n * 256 + r0) * KW + col16 * 4;
    const uint32_t sA = (uint32_t)r0 * PITCH + (uint32_t)col16 * 16;
    const uint32_t sB = (uint32_t)(128 + r0) * PITCH + (uint32_t)col16 * 16;

#define FILL_STAGE(stg_off, kc_words)                                        \
    do {                                                                     \
        uint32_t _b = sbase + (stg_off);                                     \
        const uint32_t* _ga = gA + (kc_words);                               \
        const uint32_t* _gb = gB + (kc_words);                               \
        cp_async16(_b + sA, _ga);                                            \
        cp_async16(_b + sA + 64u * PITCH, _ga + (size_t)64 * KW);            \
        cp_async16(_b + sB, _gb);                                            \
        cp_async16(_b + sB + 64u * PITCH, _gb + (size_t)64 * KW);            \
        cp_async16(_b + sB + 128u * PITCH, _gb + (size_t)128 * KW);          \
        cp_async16(_b + sB + 192u * PITCH, _gb + (size_t)192 * KW);          \
    } while (0)

    // prologue: fill stages 0, 1
#pragma unroll
    for (int s = 0; s < NST - 1; ++s) {
        FILL_STAGE(s * STG_BYTES, s * KC);
        cp_commit();
    }

    int acc[8][8];
#pragma unroll
    for (int i = 0; i < 8; ++i)
#pragma unroll
        for (int j = 0; j < 8; ++j) acc[i][j] = 0;

    const uint32_t aoff = (uint32_t)(wm * 32 + tm) * PITCH;
    const uint32_t boff = (uint32_t)(128 + wn * 64 + tn) * PITCH;

    for (int kc = 0; kc < NCHUNK; ++kc) {
        cp_wait<NST - 2>();
        __syncthreads();

        int ps = kc + NST - 1;
        if (ps < NCHUNK) FILL_STAGE((ps % NST) * STG_BYTES, ps * KC);
        cp_commit();

        const uint32_t stg = sbase + (kc % NST) * STG_BYTES;
#pragma unroll 1
        for (int k4 = 0; k4 < KC / 4; ++k4) {
            const uint32_t kb = (uint32_t)k4 * 16;
            uint4 a[8];
#pragma unroll
            for (int i = 0; i < 8; ++i)
                a[i] = lds128(stg + aoff + (uint32_t)(i * 4) * PITCH + kb);
#pragma unroll
            for (int j = 0; j < 8; ++j) {
                uint4 b = lds128(stg + boff + (uint32_t)(j * 8) * PITCH + kb);
#pragma unroll
                for (int i = 0; i < 8; ++i) {
                    mad_acc(acc[i][j], __popc(a[i].x ^ b.x), one);
                    mad_acc(acc[i][j], __popc(a[i].y ^ b.y), one);
                    mad_acc(acc[i][j], __popc(a[i].z ^ b.z), one);
                    mad_acc(acc[i][j], __popc(a[i].w ^ b.w), one);
                }
            }
        }
    }

    // ---- epilogue -------------------------------------------------------
    const int mb = tile_m * 128 + wm * 32 + tm;
    const int nb = tile_n * 256 + wn * 64 + tn;
#pragma unroll
    for (int j = 0; j < 8; ++j) {
        int n = nb + 8 * j;
        float bv = bias[n];
        float sv = g_wscale[n];
#pragma unroll
        for (int i = 0; i < 8; ++i) {
            int m = mb + 4 * i;
            float v = (float)(INF - 2 * acc[i][j]);
            out[(size_t)m * OUTF + n] = fmaxf((v + bv) * sv, 0.f);
        }
    }
}

// ---------------------------------------------------------------------------
// Launcher — GEMM is the 4th launch (0-based #3): ncu's capture slot.
// ---------------------------------------------------------------------------
extern "C" void kernel_launch(void* const* d_in, const int* in_sizes, int n_in,
                              void* d_out, int out_size) {
    (void)in_sizes; (void)n_in; (void)out_size;
    const float* x     = (const float*)d_in[0];
    const float* gamma = (const float*)d_in[1];
    const float* beta  = (const float*)d_in[2];
    const float* w     = (const float*)d_in[3];
    const float* bias  = (const float*)d_in[4];
    float* out = (float*)d_out;

    stats_partial_kernel<<<dim3(16, 32), 256>>>(x);
    stats_finalize_kernel<<<16, 256>>>(gamma, beta);
    pack_kernel<<<BATCH * 4 + OUTF, 256>>>(x, w);

    cudaFuncSetAttribute(gemm_kernel, cudaFuncAttributeMaxDynamicSharedMemorySize, GEMM_SMEM);
    gemm_kernel<<<dim3(OUTF / 256, BATCH / 128), 512, GEMM_SMEM>>>(bias, out);
}